// round 2
// baseline (speedup 1.0000x reference)
#include <cuda_runtime.h>
#include <math.h>

// Problem constants
#define D_M   1024
#define B_N   4
#define T_N   2048
#define H_N   16
#define HS_N  64
#define MROWS (B_N * T_N)   // 8192

// ---------------------------------------------------------------------------
// Scratch (static device globals — no allocation allowed). Kernels reference
// these directly via a compile-time buffer selector so kernel_launch performs
// ONLY kernel launches (no cudaGetSymbolAddress during graph capture).
// ---------------------------------------------------------------------------
__device__ float g_xn[(size_t)MROWS * D_M];
__device__ float g_t0[(size_t)MROWS * D_M];
__device__ float g_w [(size_t)MROWS * D_M];
__device__ float g_k [(size_t)MROWS * D_M];
__device__ float g_v [(size_t)MROWS * D_M];
__device__ float g_r [(size_t)MROWS * D_M];
__device__ float g_o [(size_t)MROWS * D_M];

enum Buf { BUF_XN = 0, BUF_T0, BUF_W, BUF_K, BUF_V, BUF_R, BUF_O, BUF_EXT };

template <int B> __device__ __forceinline__ float* buf_ptr(float* ext) {
    if (B == BUF_XN) return g_xn;
    if (B == BUF_T0) return g_t0;
    if (B == BUF_W)  return g_w;
    if (B == BUF_K)  return g_k;
    if (B == BUF_V)  return g_v;
    if (B == BUF_R)  return g_r;
    if (B == BUF_O)  return g_o;
    return ext;
}

// ---------------------------------------------------------------------------
// LayerNorm: one block per row (population variance, matches jnp.var ddof=0)
// Writes g_xn.
// ---------------------------------------------------------------------------
__global__ __launch_bounds__(256) void ln_kernel(
    const float* __restrict__ X, const float* __restrict__ G,
    const float* __restrict__ Bv)
{
    __shared__ float red[16];
    int row = blockIdx.x;
    int tid = threadIdx.x;
    const float* xr = X + (size_t)row * D_M;

    float4 xv = *(const float4*)(xr + tid * 4);
    float s = xv.x + xv.y + xv.z + xv.w;
    float q = xv.x * xv.x + xv.y * xv.y + xv.z * xv.z + xv.w * xv.w;

    #pragma unroll
    for (int o = 16; o > 0; o >>= 1) {
        s += __shfl_xor_sync(0xffffffffu, s, o);
        q += __shfl_xor_sync(0xffffffffu, q, o);
    }
    int wid = tid >> 5, lid = tid & 31;
    if (lid == 0) { red[wid] = s; red[8 + wid] = q; }
    __syncthreads();
    if (wid == 0) {
        float s2 = (lid < 8) ? red[lid] : 0.f;
        float q2 = (lid < 8) ? red[8 + lid] : 0.f;
        #pragma unroll
        for (int o = 4; o > 0; o >>= 1) {
            s2 += __shfl_xor_sync(0xffffffffu, s2, o);
            q2 += __shfl_xor_sync(0xffffffffu, q2, o);
        }
        if (lid == 0) { red[0] = s2; red[1] = q2; }
    }
    __syncthreads();

    float mu   = red[0] * (1.f / D_M);
    float var  = red[1] * (1.f / D_M) - mu * mu;
    float rstd = rsqrtf(var + 1e-5f);

    float4 gv = *(const float4*)(G + tid * 4);
    float4 bv = *(const float4*)(Bv + tid * 4);
    float4 yv;
    yv.x = (xv.x - mu) * rstd * gv.x + bv.x;
    yv.y = (xv.y - mu) * rstd * gv.y + bv.y;
    yv.z = (xv.z - mu) * rstd * gv.z + bv.z;
    yv.w = (xv.w - mu) * rstd * gv.w + bv.w;
    *(float4*)(g_xn + (size_t)row * D_M + tid * 4) = yv;
}

// ---------------------------------------------------------------------------
// FP32 SGEMM: C = act(A @ W (+bias)); A selected by SRC, C by DST.
// 128x128 tile, BK=16, 8x8 per thread, 256 threads.
// FLAGS: bit0 = sigmoid, bit1 = add bias
// ---------------------------------------------------------------------------
template <int SRC, int DST, int FLAGS>
__global__ __launch_bounds__(256) void gemm_kernel(
    const float* __restrict__ Wm, const float* __restrict__ bias,
    float* __restrict__ Cext)
{
    const int N = D_M, K = D_M;
    const int BM = 128, BN = 128, BK = 16;
    __shared__ float As[BK][BM + 4];
    __shared__ float Bs[BK][BN];

    const float* A = buf_ptr<SRC>(nullptr);
    float*       C = buf_ptr<DST>(Cext);

    int tid = threadIdx.x;
    int bm = blockIdx.y * BM;
    int bn = blockIdx.x * BN;
    int tm = (tid >> 4) << 3;
    int tn = (tid & 15) << 3;

    float acc[8][8];
    #pragma unroll
    for (int i = 0; i < 8; i++)
        #pragma unroll
        for (int j = 0; j < 8; j++) acc[i][j] = 0.f;

    for (int k0 = 0; k0 < K; k0 += BK) {
        #pragma unroll
        for (int j = 0; j < 2; j++) {
            int f   = tid + j * 256;
            int row = f >> 2;
            int kc  = (f & 3) << 2;
            float4 av = *(const float4*)(A + (size_t)(bm + row) * K + k0 + kc);
            As[kc + 0][row] = av.x;
            As[kc + 1][row] = av.y;
            As[kc + 2][row] = av.z;
            As[kc + 3][row] = av.w;
        }
        #pragma unroll
        for (int j = 0; j < 2; j++) {
            int f  = tid + j * 256;
            int kr = f >> 5;
            int nc = (f & 31) << 2;
            *(float4*)(&Bs[kr][nc]) =
                *(const float4*)(Wm + (size_t)(k0 + kr) * N + bn + nc);
        }
        __syncthreads();

        #pragma unroll
        for (int kk = 0; kk < BK; kk++) {
            float af[8], bf[8];
            *(float4*)(af)     = *(const float4*)(&As[kk][tm]);
            *(float4*)(af + 4) = *(const float4*)(&As[kk][tm + 4]);
            *(float4*)(bf)     = *(const float4*)(&Bs[kk][tn]);
            *(float4*)(bf + 4) = *(const float4*)(&Bs[kk][tn + 4]);
            #pragma unroll
            for (int i = 0; i < 8; i++)
                #pragma unroll
                for (int j = 0; j < 8; j++)
                    acc[i][j] = fmaf(af[i], bf[j], acc[i][j]);
        }
        __syncthreads();
    }

    float bb[8];
    #pragma unroll
    for (int j = 0; j < 8; j++)
        bb[j] = (FLAGS & 2) ? bias[bn + tn + j] : 0.f;

    #pragma unroll
    for (int i = 0; i < 8; i++) {
        float* crow = C + (size_t)(bm + tm + i) * N + bn + tn;
        float vv[8];
        #pragma unroll
        for (int j = 0; j < 8; j++) {
            float t = acc[i][j] + bb[j];
            if (FLAGS & 1) t = 1.f / (1.f + expf(-t));
            vv[j] = t;
        }
        *(float4*)(crow)     = *(float4*)(vv);
        *(float4*)(crow + 4) = *(float4*)(vv + 4);
    }
}

// ---------------------------------------------------------------------------
// Selective-WKV scan. Grid = 128 blocks: (b, h, e-half). 256 threads.
// Thread t: e_local = t>>3 (32 cols/block), dq = t&7 (8 rows of 8 d-values).
// State s[8] in registers; out[e] reduced over dq via shfl_xor.
// Reads g_k/g_v/g_w/g_r, writes g_o + final state into Sout.
// ---------------------------------------------------------------------------
__device__ __forceinline__ void ld8(const float* __restrict__ p, float* d) {
    float4 a = *(const float4*)(p);
    float4 b = *(const float4*)(p + 4);
    d[0] = a.x; d[1] = a.y; d[2] = a.z; d[3] = a.w;
    d[4] = b.x; d[5] = b.y; d[6] = b.z; d[7] = b.w;
}

__global__ __launch_bounds__(256) void scan_kernel(float* __restrict__ Sout)
{
    int blk = blockIdx.x;
    int eh = blk & 1;
    int bh = blk >> 1;
    int b  = bh >> 4;
    int h  = bh & 15;
    int tid = threadIdx.x;
    int el  = tid >> 3;
    int dq  = tid & 7;
    int e   = eh * 32 + el;

    size_t base = ((size_t)b * T_N) * D_M + h * HS_N;
    const float* kp = g_k + base + dq * 8;
    const float* wp = g_w + base + dq * 8;
    const float* rp = g_r + base + dq * 8;
    const float* vp = g_v + base + e;
    float*       op = g_o + base + e;

    float s[8];
    #pragma unroll
    for (int i = 0; i < 8; i++) s[i] = 0.f;

    float kc[8], wc[8], rc[8], vc;
    ld8(kp, kc); ld8(wp, wc); ld8(rp, rc); vc = *vp;

    for (int tt = 0; tt < T_N; tt++) {
        int nn = (tt < T_N - 1) ? D_M : 0;   // last iter re-reads (unused)
        float kn[8], wn[8], rn[8], vn;
        ld8(kp + nn, kn); ld8(wp + nn, wn); ld8(rp + nn, rn); vn = vp[nn];

        float acc = 0.f;
        #pragma unroll
        for (int i = 0; i < 8; i++) {
            float si = s[i];
            si = fmaf(kc[i], vc, fmaf(-wc[i], si, si));  // (1-w)*s + k*v
            s[i] = si;
            acc = fmaf(rc[i], si, acc);
        }
        acc += __shfl_xor_sync(0xffffffffu, acc, 1);
        acc += __shfl_xor_sync(0xffffffffu, acc, 2);
        acc += __shfl_xor_sync(0xffffffffu, acc, 4);
        if (dq == 0) *op = acc;

        kp += D_M; wp += D_M; rp += D_M; vp += D_M; op += D_M;
        #pragma unroll
        for (int i = 0; i < 8; i++) { kc[i] = kn[i]; wc[i] = wn[i]; rc[i] = rn[i]; }
        vc = vn;
    }

    // final state layout: state[b][h][d][e], d = dq*8 + i
    size_t sb = (((size_t)b * H_N + h) * HS_N + dq * 8) * HS_N + e;
    #pragma unroll
    for (int i = 0; i < 8; i++) Sout[sb + (size_t)i * HS_N] = s[i];
}

// ---------------------------------------------------------------------------
// Launch — kernel launches ONLY (graph-capture safe)
// ---------------------------------------------------------------------------
extern "C" void kernel_launch(void* const* d_in, const int* in_sizes, int n_in,
                              void* d_out, int out_size)
{
    const float* x    = (const float*)d_in[0];
    const float* ln_g = (const float*)d_in[1];
    const float* ln_b = (const float*)d_in[2];
    const float* Wx   = (const float*)d_in[3];
    const float* Ww   = (const float*)d_in[4];
    const float* bw   = (const float*)d_in[5];
    const float* Wk   = (const float*)d_in[6];
    const float* Wv   = (const float*)d_in[7];
    const float* Wr   = (const float*)d_in[8];
    const float* Wo   = (const float*)d_in[9];
    float* out = (float*)d_out;

    // 1) LayerNorm -> g_xn
    ln_kernel<<<MROWS, 256>>>(x, ln_g, ln_b);

    // 2) Projections
    dim3 grid(D_M / 128, MROWS / 128);
    gemm_kernel<BUF_XN, BUF_T0, 0><<<grid, 256>>>(Wx, nullptr, nullptr); // xn@Wx
    gemm_kernel<BUF_T0, BUF_W,  3><<<grid, 256>>>(Ww, bw,      nullptr); // sig(+bw)
    gemm_kernel<BUF_XN, BUF_K,  0><<<grid, 256>>>(Wk, nullptr, nullptr); // k
    gemm_kernel<BUF_XN, BUF_V,  0><<<grid, 256>>>(Wv, nullptr, nullptr); // v
    gemm_kernel<BUF_XN, BUF_R,  1><<<grid, 256>>>(Wr, nullptr, nullptr); // r=sig

    // 3) Sequential WKV scan -> g_o, final state -> tail of d_out
    scan_kernel<<<128, 256>>>(out + (size_t)MROWS * D_M);

    // 4) Output projection y = g_o @ Wo -> head of d_out
    gemm_kernel<BUF_O, BUF_EXT, 0><<<grid, 256>>>(Wo, nullptr, out);
}

// round 3
// speedup vs baseline: 2.3108x; 2.3108x over previous
#include <cuda_runtime.h>
#include <math.h>
#include <stdint.h>

// Problem constants
#define D_M   1024
#define B_N   4
#define T_N   2048
#define H_N   16
#define HS_N  64
#define MROWS (B_N * T_N)   // 8192

// ---------------------------------------------------------------------------
// Scratch (static device globals)
// ---------------------------------------------------------------------------
__device__ float g_xn[(size_t)MROWS * D_M];
__device__ float g_t0[(size_t)MROWS * D_M];
__device__ float g_w [(size_t)MROWS * D_M];
__device__ float g_k [(size_t)MROWS * D_M];
__device__ float g_v [(size_t)MROWS * D_M];
__device__ float g_r [(size_t)MROWS * D_M];
__device__ float g_o [(size_t)MROWS * D_M];

enum Buf { BUF_XN = 0, BUF_T0, BUF_W, BUF_K, BUF_V, BUF_R, BUF_O, BUF_EXT };

template <int B> __device__ __forceinline__ float* buf_ptr(float* ext) {
    if (B == BUF_XN) return g_xn;
    if (B == BUF_T0) return g_t0;
    if (B == BUF_W)  return g_w;
    if (B == BUF_K)  return g_k;
    if (B == BUF_V)  return g_v;
    if (B == BUF_R)  return g_r;
    if (B == BUF_O)  return g_o;
    return ext;
}

// ---------------------------------------------------------------------------
// PTX helpers: cp.async + tf32 mma
// ---------------------------------------------------------------------------
__device__ __forceinline__ void cp16(void* smem_dst, const void* gsrc) {
    uint32_t s = (uint32_t)__cvta_generic_to_shared(smem_dst);
    asm volatile("cp.async.cg.shared.global [%0], [%1], 16;\n" :: "r"(s), "l"(gsrc));
}
#define CP_COMMIT() asm volatile("cp.async.commit_group;\n" ::: "memory")
template <int N> __device__ __forceinline__ void cp_wait() {
    asm volatile("cp.async.wait_group %0;\n" :: "n"(N) : "memory");
}
__device__ __forceinline__ uint32_t to_tf32(float x) {
    uint32_t r;
    asm("cvt.rna.tf32.f32 %0, %1;\n" : "=r"(r) : "f"(x));
    return r;
}
__device__ __forceinline__ void mma_tf32(float* c, const uint32_t* a, const uint32_t* b) {
    asm volatile(
        "mma.sync.aligned.m16n8k8.row.col.f32.tf32.tf32.f32 "
        "{%0,%1,%2,%3}, {%4,%5,%6,%7}, {%8,%9}, {%0,%1,%2,%3};\n"
        : "+f"(c[0]), "+f"(c[1]), "+f"(c[2]), "+f"(c[3])
        : "r"(a[0]), "r"(a[1]), "r"(a[2]), "r"(a[3]), "r"(b[0]), "r"(b[1]));
}

// ---------------------------------------------------------------------------
// LayerNorm (unchanged — correct & cheap)
// ---------------------------------------------------------------------------
__global__ __launch_bounds__(256) void ln_kernel(
    const float* __restrict__ X, const float* __restrict__ G,
    const float* __restrict__ Bv)
{
    __shared__ float red[16];
    int row = blockIdx.x;
    int tid = threadIdx.x;
    const float* xr = X + (size_t)row * D_M;

    float4 xv = *(const float4*)(xr + tid * 4);
    float s = xv.x + xv.y + xv.z + xv.w;
    float q = xv.x * xv.x + xv.y * xv.y + xv.z * xv.z + xv.w * xv.w;

    #pragma unroll
    for (int o = 16; o > 0; o >>= 1) {
        s += __shfl_xor_sync(0xffffffffu, s, o);
        q += __shfl_xor_sync(0xffffffffu, q, o);
    }
    int wid = tid >> 5, lid = tid & 31;
    if (lid == 0) { red[wid] = s; red[8 + wid] = q; }
    __syncthreads();
    if (wid == 0) {
        float s2 = (lid < 8) ? red[lid] : 0.f;
        float q2 = (lid < 8) ? red[8 + lid] : 0.f;
        #pragma unroll
        for (int o = 4; o > 0; o >>= 1) {
            s2 += __shfl_xor_sync(0xffffffffu, s2, o);
            q2 += __shfl_xor_sync(0xffffffffu, q2, o);
        }
        if (lid == 0) { red[0] = s2; red[1] = q2; }
    }
    __syncthreads();

    float mu   = red[0] * (1.f / D_M);
    float var  = red[1] * (1.f / D_M) - mu * mu;
    float rstd = rsqrtf(var + 1e-5f);

    float4 gv = *(const float4*)(G + tid * 4);
    float4 bv = *(const float4*)(Bv + tid * 4);
    float4 yv;
    yv.x = (xv.x - mu) * rstd * gv.x + bv.x;
    yv.y = (xv.y - mu) * rstd * gv.y + bv.y;
    yv.z = (xv.z - mu) * rstd * gv.z + bv.z;
    yv.w = (xv.w - mu) * rstd * gv.w + bv.w;
    *(float4*)(g_xn + (size_t)row * D_M + tid * 4) = yv;
}

// ---------------------------------------------------------------------------
// TF32 tensor-core GEMM: C = act(A @ W (+bias))
// 128x128 block tile, BK=16, 2-stage cp.async, 8 warps, warp = 64x32,
// per warp 4x4 m16n8k8 fragments.  FLAGS: bit0 sigmoid, bit1 bias.
// Smem pads chosen for conflict-free fragment LDS:
//   A[128][20]: bank=(20*m + k)%32 -> unique over (g,c)
//   B[16][136]: bank=(136*k + n)%32 = (8k + n)%32 -> unique over (c,g)
// ---------------------------------------------------------------------------
template <int SRC, int DST, int FLAGS>
__global__ __launch_bounds__(256) void gemm_tc(
    const float* __restrict__ Wm, const float* __restrict__ bias,
    float* __restrict__ Cext)
{
    constexpr int N = D_M, K = D_M;
    constexpr int AP = 20, BP = 136;
    __shared__ float As[2][128][AP];
    __shared__ float Bs[2][16][BP];

    const float* A = buf_ptr<SRC>(nullptr);
    float*       C = buf_ptr<DST>(Cext);

    int tid  = threadIdx.x;
    int wid  = tid >> 5, lane = tid & 31;
    int g    = lane >> 2, cq = lane & 3;
    int bm   = blockIdx.y * 128, bn = blockIdx.x * 128;
    int wm   = (wid & 1) * 64,   wn = (wid >> 1) * 32;

    // cp.async source/dest indices (per thread: 2 float4 for A, 2 for B)
    int ar = tid >> 1;            // A row 0..127
    int ac = (tid & 1) * 8;       // A col 0 or 8
    int br = tid >> 4;            // B k-row 0..15
    int bc = (tid & 15) * 8;      // B col 0..120

    const float* Abase = A + (size_t)(bm + ar) * K + ac;
    const float* Bbase = Wm + (size_t)br * N + bn + bc;

    float acc[4][4][4];
    #pragma unroll
    for (int mi = 0; mi < 4; mi++)
        #pragma unroll
        for (int ni = 0; ni < 4; ni++)
            #pragma unroll
            for (int x = 0; x < 4; x++) acc[mi][ni][x] = 0.f;

    // prologue: stage 0
    cp16(&As[0][ar][ac],     Abase);
    cp16(&As[0][ar][ac + 4], Abase + 4);
    cp16(&Bs[0][br][bc],     Bbase);
    cp16(&Bs[0][br][bc + 4], Bbase + 4);
    CP_COMMIT();

    for (int kt = 0; kt < K / 16; kt++) {
        int buf = kt & 1;
        if (kt < K / 16 - 1) {
            int k0 = (kt + 1) * 16;
            cp16(&As[buf ^ 1][ar][ac],     Abase + k0);
            cp16(&As[buf ^ 1][ar][ac + 4], Abase + k0 + 4);
            cp16(&Bs[buf ^ 1][br][bc],     Bbase + (size_t)k0 * N);
            cp16(&Bs[buf ^ 1][br][bc + 4], Bbase + (size_t)k0 * N + 4);
            CP_COMMIT();
            cp_wait<1>();
        } else {
            cp_wait<0>();
        }
        __syncthreads();

        #pragma unroll
        for (int ks = 0; ks < 2; ks++) {
            uint32_t af[4][4], bf[4][2];
            #pragma unroll
            for (int mi = 0; mi < 4; mi++) {
                int r0 = wm + mi * 16 + g;
                af[mi][0] = to_tf32(As[buf][r0    ][ks * 8 + cq]);
                af[mi][1] = to_tf32(As[buf][r0 + 8][ks * 8 + cq]);
                af[mi][2] = to_tf32(As[buf][r0    ][ks * 8 + cq + 4]);
                af[mi][3] = to_tf32(As[buf][r0 + 8][ks * 8 + cq + 4]);
            }
            #pragma unroll
            for (int ni = 0; ni < 4; ni++) {
                int c0 = wn + ni * 8 + g;
                bf[ni][0] = to_tf32(Bs[buf][ks * 8 + cq    ][c0]);
                bf[ni][1] = to_tf32(Bs[buf][ks * 8 + cq + 4][c0]);
            }
            #pragma unroll
            for (int mi = 0; mi < 4; mi++)
                #pragma unroll
                for (int ni = 0; ni < 4; ni++)
                    mma_tf32(acc[mi][ni], af[mi], bf[ni]);
        }
        __syncthreads();
    }

    // Epilogue: C fragment (g, cq*2), (g, cq*2+1), (g+8, ...), (g+8, ...+1)
    #pragma unroll
    for (int mi = 0; mi < 4; mi++) {
        int row0 = bm + wm + mi * 16 + g;
        #pragma unroll
        for (int ni = 0; ni < 4; ni++) {
            int col = bn + wn + ni * 8 + cq * 2;
            float b0 = (FLAGS & 2) ? bias[col]     : 0.f;
            float b1 = (FLAGS & 2) ? bias[col + 1] : 0.f;
            float v0 = acc[mi][ni][0] + b0;
            float v1 = acc[mi][ni][1] + b1;
            float v2 = acc[mi][ni][2] + b0;
            float v3 = acc[mi][ni][3] + b1;
            if (FLAGS & 1) {
                v0 = 1.f / (1.f + expf(-v0));
                v1 = 1.f / (1.f + expf(-v1));
                v2 = 1.f / (1.f + expf(-v2));
                v3 = 1.f / (1.f + expf(-v3));
            }
            float2 lo = make_float2(v0, v1);
            float2 hi = make_float2(v2, v3);
            *(float2*)(C + (size_t)row0 * N + col)       = lo;
            *(float2*)(C + (size_t)(row0 + 8) * N + col) = hi;
        }
    }
}

// ---------------------------------------------------------------------------
// Selective-WKV scan with 8-stage cp.async smem pipeline.
// Grid = 128 blocks (b, h, e-half), 256 threads.
// Threads 0..63 stream step t+7 (k,w,r,v rows: 4 x 64 floats = 1KB/stage);
// all threads compute step t from smem. One __syncthreads per step.
// Thread t: el = t>>3 (32 e-cols), dq = t&7 (8 d-rows of 8).
// ---------------------------------------------------------------------------
#define SC_ST 8

__global__ __launch_bounds__(256) void scan_kernel(float* __restrict__ Sout)
{
    __shared__ float sh[SC_ST][256];   // per stage: k[64] w[64] r[64] v[64]

    int blk = blockIdx.x;
    int eh = blk & 1;
    int bh = blk >> 1;
    int b  = bh >> 4;
    int h  = bh & 15;
    int tid = threadIdx.x;
    int el  = tid >> 3;
    int dq  = tid & 7;
    int e   = eh * 32 + el;

    size_t base = (size_t)b * T_N * D_M + h * HS_N;

    // loader role: 64 threads, one float4 each per stage
    bool loader = (tid < 64);
    int  la = tid >> 4;            // 0:k 1:w 2:r 3:v
    int  lc = (tid & 15) * 4;      // float offset within 64
    const float* lp = g_k + base;  // default; fixed below
    if (la == 1) lp = g_w + base;
    else if (la == 2) lp = g_r + base;
    else if (la == 3) lp = g_v + base;
    lp += lc;

    // prologue: stages 0..6
    #pragma unroll
    for (int s = 0; s < SC_ST - 1; s++) {
        if (loader) cp16(&sh[s][la * 64 + lc], lp + (size_t)s * D_M);
        CP_COMMIT();
    }

    float st[8];
    #pragma unroll
    for (int i = 0; i < 8; i++) st[i] = 0.f;

    float* op = g_o + base + e;

    for (int tt = 0; tt < T_N; tt++) {
        cp_wait<SC_ST - 2>();
        __syncthreads();

        // issue stage tt+7 (overwrites slot consumed at tt-1; barrier protects)
        int tn = tt + SC_ST - 1;
        if (loader && tn < T_N) cp16(&sh[tn & (SC_ST - 1)][la * 64 + lc],
                                     lp + (size_t)tn * D_M);
        CP_COMMIT();

        const float* sp = &sh[tt & (SC_ST - 1)][0];
        float4 k0 = *(const float4*)(sp + dq * 8);
        float4 k1 = *(const float4*)(sp + dq * 8 + 4);
        float4 w0 = *(const float4*)(sp + 64 + dq * 8);
        float4 w1 = *(const float4*)(sp + 64 + dq * 8 + 4);
        float4 r0 = *(const float4*)(sp + 128 + dq * 8);
        float4 r1 = *(const float4*)(sp + 128 + dq * 8 + 4);
        float vv  = sp[192 + e];

        float kc[8] = {k0.x, k0.y, k0.z, k0.w, k1.x, k1.y, k1.z, k1.w};
        float wc[8] = {w0.x, w0.y, w0.z, w0.w, w1.x, w1.y, w1.z, w1.w};
        float rc[8] = {r0.x, r0.y, r0.z, r0.w, r1.x, r1.y, r1.z, r1.w};

        float acc = 0.f;
        #pragma unroll
        for (int i = 0; i < 8; i++) {
            float si = st[i];
            si = fmaf(kc[i], vv, fmaf(-wc[i], si, si));  // (1-w)*s + k*v
            st[i] = si;
            acc = fmaf(rc[i], si, acc);
        }
        acc += __shfl_xor_sync(0xffffffffu, acc, 1);
        acc += __shfl_xor_sync(0xffffffffu, acc, 2);
        acc += __shfl_xor_sync(0xffffffffu, acc, 4);
        if (dq == 0) *op = acc;
        op += D_M;
    }

    // final state layout: state[b][h][d][e], d = dq*8 + i
    size_t sb = (((size_t)b * H_N + h) * HS_N + dq * 8) * HS_N + e;
    #pragma unroll
    for (int i = 0; i < 8; i++) Sout[sb + (size_t)i * HS_N] = st[i];
}

// ---------------------------------------------------------------------------
// Launch — kernel launches ONLY (graph-capture safe)
// ---------------------------------------------------------------------------
extern "C" void kernel_launch(void* const* d_in, const int* in_sizes, int n_in,
                              void* d_out, int out_size)
{
    const float* x    = (const float*)d_in[0];
    const float* ln_g = (const float*)d_in[1];
    const float* ln_b = (const float*)d_in[2];
    const float* Wx   = (const float*)d_in[3];
    const float* Ww   = (const float*)d_in[4];
    const float* bw   = (const float*)d_in[5];
    const float* Wk   = (const float*)d_in[6];
    const float* Wv   = (const float*)d_in[7];
    const float* Wr   = (const float*)d_in[8];
    const float* Wo   = (const float*)d_in[9];
    float* out = (float*)d_out;

    // 1) LayerNorm -> g_xn
    ln_kernel<<<MROWS, 256>>>(x, ln_g, ln_b);

    // 2) Projections (tf32 tensor cores)
    dim3 grid(D_M / 128, MROWS / 128);
    gemm_tc<BUF_XN, BUF_T0, 0><<<grid, 256>>>(Wx, nullptr, nullptr); // xn@Wx
    gemm_tc<BUF_T0, BUF_W,  3><<<grid, 256>>>(Ww, bw,      nullptr); // sig(+bw)
    gemm_tc<BUF_XN, BUF_K,  0><<<grid, 256>>>(Wk, nullptr, nullptr); // k
    gemm_tc<BUF_XN, BUF_V,  0><<<grid, 256>>>(Wv, nullptr, nullptr); // v
    gemm_tc<BUF_XN, BUF_R,  1><<<grid, 256>>>(Wr, nullptr, nullptr); // r=sig

    // 3) Sequential WKV scan -> g_o, final state -> tail of d_out
    scan_kernel<<<128, 256>>>(out + (size_t)MROWS * D_M);

    // 4) Output projection y = g_o @ Wo -> head of d_out
    gemm_tc<BUF_O, BUF_EXT, 0><<<grid, 256>>>(Wo, nullptr, out);
}

// round 4
// speedup vs baseline: 2.9857x; 1.2921x over previous
#include <cuda_runtime.h>
#include <math.h>
#include <stdint.h>

// Problem constants
#define D_M   1024
#define B_N   4
#define T_N   2048
#define H_N   16
#define HS_N  64
#define MROWS (B_N * T_N)   // 8192
#define CH_L  32            // chunk length
#define CH_N  (T_N / CH_L)  // 64 chunks
#define BH_N  (B_N * H_N)   // 64

// ---------------------------------------------------------------------------
// Scratch (static device globals)
// ---------------------------------------------------------------------------
__device__ float g_xn[(size_t)MROWS * D_M];
__device__ float g_t0[(size_t)MROWS * D_M];
__device__ float g_w [(size_t)MROWS * D_M];
__device__ float g_k [(size_t)MROWS * D_M];
__device__ float g_v [(size_t)MROWS * D_M];
__device__ float g_r [(size_t)MROWS * D_M];   // becomes q after pass A
__device__ float g_o [(size_t)MROWS * D_M];
__device__ float g_wt[(size_t)6 * D_M * D_M];            // tf32-rounded weights
__device__ float g_sloc[(size_t)BH_N * CH_N * HS_N * HS_N]; // [bh][ch][e][d]
__device__ float g_sin [(size_t)BH_N * CH_N * HS_N * HS_N]; // [bh][ch][e][d]
__device__ float g_pc  [(size_t)BH_N * CH_N * HS_N];        // [bh][ch][d]

enum Buf { BUF_XN = 0, BUF_T0, BUF_O, BUF_W, BUF_K, BUF_V, BUF_R, BUF_EXT };

template <int B> __device__ __forceinline__ float* buf_ptr(float* ext) {
    if (B == BUF_XN) return g_xn;
    if (B == BUF_T0) return g_t0;
    if (B == BUF_W)  return g_w;
    if (B == BUF_K)  return g_k;
    if (B == BUF_V)  return g_v;
    if (B == BUF_R)  return g_r;
    if (B == BUF_O)  return g_o;
    return ext;
}

// ---------------------------------------------------------------------------
// PTX helpers
// ---------------------------------------------------------------------------
__device__ __forceinline__ void cp16(void* smem_dst, const void* gsrc) {
    uint32_t s = (uint32_t)__cvta_generic_to_shared(smem_dst);
    asm volatile("cp.async.cg.shared.global [%0], [%1], 16;\n" :: "r"(s), "l"(gsrc));
}
#define CP_COMMIT() asm volatile("cp.async.commit_group;\n" ::: "memory")
template <int N> __device__ __forceinline__ void cp_wait() {
    asm volatile("cp.async.wait_group %0;\n" :: "n"(N) : "memory");
}
__device__ __forceinline__ float to_tf32f(float x) {
    uint32_t r;
    asm("cvt.rna.tf32.f32 %0, %1;\n" : "=r"(r) : "f"(x));
    return __uint_as_float(r);
}
__device__ __forceinline__ void mma_tf32(float* c, const uint32_t* a, const uint32_t* b) {
    asm volatile(
        "mma.sync.aligned.m16n8k8.row.col.f32.tf32.tf32.f32 "
        "{%0,%1,%2,%3}, {%4,%5,%6,%7}, {%8,%9}, {%0,%1,%2,%3};\n"
        : "+f"(c[0]), "+f"(c[1]), "+f"(c[2]), "+f"(c[3])
        : "r"(a[0]), "r"(a[1]), "r"(a[2]), "r"(a[3]), "r"(b[0]), "r"(b[1]));
}

// ---------------------------------------------------------------------------
// Round 6 weight matrices to tf32 into g_wt. grid 1024 x 256.
// ---------------------------------------------------------------------------
__global__ __launch_bounds__(256) void round_w_kernel(
    const float* __restrict__ w0, const float* __restrict__ w1,
    const float* __restrict__ w2, const float* __restrict__ w3,
    const float* __restrict__ w4, const float* __restrict__ w5)
{
    const float* srcs[6] = {w0, w1, w2, w3, w4, w5};
    size_t idx = ((size_t)blockIdx.x * 256 + threadIdx.x) * 4;
    #pragma unroll
    for (int i = 0; i < 6; i++) {
        float4 v = *(const float4*)(srcs[i] + idx);
        v.x = to_tf32f(v.x); v.y = to_tf32f(v.y);
        v.z = to_tf32f(v.z); v.w = to_tf32f(v.w);
        *(float4*)(g_wt + (size_t)i * D_M * D_M + idx) = v;
    }
}

// ---------------------------------------------------------------------------
// LayerNorm -> g_xn (tf32-rounded: feeds GEMMs only)
// ---------------------------------------------------------------------------
__global__ __launch_bounds__(256) void ln_kernel(
    const float* __restrict__ X, const float* __restrict__ G,
    const float* __restrict__ Bv)
{
    __shared__ float red[16];
    int row = blockIdx.x;
    int tid = threadIdx.x;
    const float* xr = X + (size_t)row * D_M;

    float4 xv = *(const float4*)(xr + tid * 4);
    float s = xv.x + xv.y + xv.z + xv.w;
    float q = xv.x * xv.x + xv.y * xv.y + xv.z * xv.z + xv.w * xv.w;

    #pragma unroll
    for (int o = 16; o > 0; o >>= 1) {
        s += __shfl_xor_sync(0xffffffffu, s, o);
        q += __shfl_xor_sync(0xffffffffu, q, o);
    }
    int wid = tid >> 5, lid = tid & 31;
    if (lid == 0) { red[wid] = s; red[8 + wid] = q; }
    __syncthreads();
    if (wid == 0) {
        float s2 = (lid < 8) ? red[lid] : 0.f;
        float q2 = (lid < 8) ? red[8 + lid] : 0.f;
        #pragma unroll
        for (int o = 4; o > 0; o >>= 1) {
            s2 += __shfl_xor_sync(0xffffffffu, s2, o);
            q2 += __shfl_xor_sync(0xffffffffu, q2, o);
        }
        if (lid == 0) { red[0] = s2; red[1] = q2; }
    }
    __syncthreads();

    float mu   = red[0] * (1.f / D_M);
    float var  = red[1] * (1.f / D_M) - mu * mu;
    float rstd = rsqrtf(var + 1e-5f);

    float4 gv = *(const float4*)(G + tid * 4);
    float4 bv = *(const float4*)(Bv + tid * 4);
    float4 yv;
    yv.x = to_tf32f((xv.x - mu) * rstd * gv.x + bv.x);
    yv.y = to_tf32f((xv.y - mu) * rstd * gv.y + bv.y);
    yv.z = to_tf32f((xv.z - mu) * rstd * gv.z + bv.z);
    yv.w = to_tf32f((xv.w - mu) * rstd * gv.w + bv.w);
    *(float4*)(g_xn + (size_t)row * D_M + tid * 4) = yv;
}

// ---------------------------------------------------------------------------
// TF32 tensor-core GEMM: C = act(A @ W (+bias)); operands pre-rounded.
// 128x128 tile, BK=16, 2-stage cp.async, 4 warps (128 thr), warp = 64x64.
// FLAGS: bit0 sigmoid, bit1 bias, bit2 round output to tf32.
// ---------------------------------------------------------------------------
template <int SRC, int DST, int WIDX, int FLAGS>
__global__ __launch_bounds__(128) void gemm_tc(
    const float* __restrict__ bias, float* __restrict__ Cext)
{
    constexpr int N = D_M, K = D_M;
    constexpr int AP = 20, BP = 136;
    __shared__ float As[2][128][AP];
    __shared__ float Bs[2][16][BP];

    const float* A  = buf_ptr<SRC>(nullptr);
    const float* Wm = g_wt + (size_t)WIDX * D_M * D_M;
    float*       C  = buf_ptr<DST>(Cext);

    int tid  = threadIdx.x;
    int wid  = tid >> 5, lane = tid & 31;
    int g    = lane >> 2, cq = lane & 3;
    int bm   = blockIdx.y * 128, bn = blockIdx.x * 128;
    int wm   = (wid & 1) * 64,   wn = (wid >> 1) * 64;

    // cp.async indices: per thread 4 float4 for A, 4 for B
    int ar = tid >> 1;           // via f = tid + j*128: row = f>>2? recompute below
    (void)ar;

    float acc[4][8][4];
    #pragma unroll
    for (int mi = 0; mi < 4; mi++)
        #pragma unroll
        for (int ni = 0; ni < 8; ni++)
            #pragma unroll
            for (int x = 0; x < 4; x++) acc[mi][ni][x] = 0.f;

    auto load_stage = [&](int buf, int k0) {
        #pragma unroll
        for (int j = 0; j < 4; j++) {
            int f   = tid + j * 128;        // 0..511
            int row = f >> 2;
            int kc  = (f & 3) << 2;
            cp16(&As[buf][row][kc], A + (size_t)(bm + row) * K + k0 + kc);
        }
        #pragma unroll
        for (int j = 0; j < 4; j++) {
            int f  = tid + j * 128;
            int kr = f >> 5;
            int nc = (f & 31) << 2;
            cp16(&Bs[buf][kr][nc], Wm + (size_t)(k0 + kr) * N + bn + nc);
        }
        CP_COMMIT();
    };

    load_stage(0, 0);

    for (int kt = 0; kt < K / 16; kt++) {
        int buf = kt & 1;
        if (kt < K / 16 - 1) {
            load_stage(buf ^ 1, (kt + 1) * 16);
            cp_wait<1>();
        } else {
            cp_wait<0>();
        }
        __syncthreads();

        #pragma unroll
        for (int ks = 0; ks < 2; ks++) {
            uint32_t af[4][4], bf[8][2];
            #pragma unroll
            for (int mi = 0; mi < 4; mi++) {
                int r0 = wm + mi * 16 + g;
                af[mi][0] = *(const uint32_t*)&As[buf][r0    ][ks * 8 + cq];
                af[mi][1] = *(const uint32_t*)&As[buf][r0 + 8][ks * 8 + cq];
                af[mi][2] = *(const uint32_t*)&As[buf][r0    ][ks * 8 + cq + 4];
                af[mi][3] = *(const uint32_t*)&As[buf][r0 + 8][ks * 8 + cq + 4];
            }
            #pragma unroll
            for (int ni = 0; ni < 8; ni++) {
                int c0 = wn + ni * 8 + g;
                bf[ni][0] = *(const uint32_t*)&Bs[buf][ks * 8 + cq    ][c0];
                bf[ni][1] = *(const uint32_t*)&Bs[buf][ks * 8 + cq + 4][c0];
            }
            #pragma unroll
            for (int mi = 0; mi < 4; mi++)
                #pragma unroll
                for (int ni = 0; ni < 8; ni++)
                    mma_tf32(acc[mi][ni], af[mi], bf[ni]);
        }
        __syncthreads();
    }

    #pragma unroll
    for (int mi = 0; mi < 4; mi++) {
        int row0 = bm + wm + mi * 16 + g;
        #pragma unroll
        for (int ni = 0; ni < 8; ni++) {
            int col = bn + wn + ni * 8 + cq * 2;
            float b0 = (FLAGS & 2) ? bias[col]     : 0.f;
            float b1 = (FLAGS & 2) ? bias[col + 1] : 0.f;
            float v0 = acc[mi][ni][0] + b0;
            float v1 = acc[mi][ni][1] + b1;
            float v2 = acc[mi][ni][2] + b0;
            float v3 = acc[mi][ni][3] + b1;
            if (FLAGS & 1) {
                v0 = 1.f / (1.f + expf(-v0));
                v1 = 1.f / (1.f + expf(-v1));
                v2 = 1.f / (1.f + expf(-v2));
                v3 = 1.f / (1.f + expf(-v3));
            }
            if (FLAGS & 4) {
                v0 = to_tf32f(v0); v1 = to_tf32f(v1);
                v2 = to_tf32f(v2); v3 = to_tf32f(v3);
            }
            *(float2*)(C + (size_t)row0 * N + col)       = make_float2(v0, v1);
            *(float2*)(C + (size_t)(row0 + 8) * N + col) = make_float2(v2, v3);
        }
    }
}

// ---------------------------------------------------------------------------
// Pass A: per-chunk local scan. grid (BH_N, CH_N), 512 threads.
// Thread: e = tid>>3 (64), dq = tid&7 (8 d-rows of 8). Stages chunk to smem.
// Emits: out_loc -> g_o, q = r*cumdecay -> g_r (in place), s_loc, P_c.
// ---------------------------------------------------------------------------
__global__ __launch_bounds__(512) void scan_chunk_kernel()
{
    __shared__ float sk[CH_L][64], sw[CH_L][64], sr[CH_L][64], sv[CH_L][64];

    int bh = blockIdx.x, ch = blockIdx.y;
    int b = bh >> 4, h = bh & 15;
    int tid = threadIdx.x;
    int e = tid >> 3, dq = tid & 7;

    size_t base = (size_t)b * T_N * D_M + (size_t)ch * CH_L * D_M + h * HS_N;

    // stage chunk: 4 arrays x 2048 floats; each thread 1 float4 per array
    {
        int t = tid >> 4, c = (tid & 15) * 4;
        size_t off = base + (size_t)t * D_M + c;
        cp16(&sk[t][c], g_k + off);
        cp16(&sw[t][c], g_w + off);
        cp16(&sr[t][c], g_r + off);
        cp16(&sv[t][c], g_v + off);
    }
    CP_COMMIT();
    cp_wait<0>();
    __syncthreads();

    float s[8], cum[8];
    #pragma unroll
    for (int i = 0; i < 8; i++) { s[i] = 0.f; cum[i] = 1.f; }

    float* op = g_o + base + e;
    float* qp = g_r + base + dq * 8;

    for (int t = 0; t < CH_L; t++) {
        float4 k0 = *(const float4*)&sk[t][dq * 8];
        float4 k1 = *(const float4*)&sk[t][dq * 8 + 4];
        float4 w0 = *(const float4*)&sw[t][dq * 8];
        float4 w1 = *(const float4*)&sw[t][dq * 8 + 4];
        float4 r0 = *(const float4*)&sr[t][dq * 8];
        float4 r1 = *(const float4*)&sr[t][dq * 8 + 4];
        float vv  = sv[t][e];

        float kc[8] = {k0.x, k0.y, k0.z, k0.w, k1.x, k1.y, k1.z, k1.w};
        float wc[8] = {w0.x, w0.y, w0.z, w0.w, w1.x, w1.y, w1.z, w1.w};
        float rc[8] = {r0.x, r0.y, r0.z, r0.w, r1.x, r1.y, r1.z, r1.w};

        float acc = 0.f;
        #pragma unroll
        for (int i = 0; i < 8; i++) {
            float omw = 1.f - wc[i];
            cum[i] *= omw;
            float si = fmaf(kc[i], vv, s[i] * omw);
            s[i] = si;
            acc = fmaf(rc[i], si, acc);
        }
        acc += __shfl_xor_sync(0xffffffffu, acc, 1);
        acc += __shfl_xor_sync(0xffffffffu, acc, 2);
        acc += __shfl_xor_sync(0xffffffffu, acc, 4);
        if (dq == 0) *op = acc;
        op += D_M;

        if (e == 0) {   // q_t[d] = r_t[d] * cum_t[d]  (threads 0..7)
            float q[8];
            #pragma unroll
            for (int i = 0; i < 8; i++) q[i] = rc[i] * cum[i];
            *(float4*)(qp)     = make_float4(q[0], q[1], q[2], q[3]);
            *(float4*)(qp + 4) = make_float4(q[4], q[5], q[6], q[7]);
        }
        qp += D_M;
    }

    // s_loc layout [bh][ch][e][d]
    size_t sb = ((size_t)bh * CH_N + ch) * (HS_N * HS_N) + (size_t)e * HS_N + dq * 8;
    *(float4*)(g_sloc + sb)     = make_float4(s[0], s[1], s[2], s[3]);
    *(float4*)(g_sloc + sb + 4) = make_float4(s[4], s[5], s[6], s[7]);

    if (e == 0) {
        size_t pb = ((size_t)bh * CH_N + ch) * HS_N + dq * 8;
        *(float4*)(g_pc + pb)     = make_float4(cum[0], cum[1], cum[2], cum[3]);
        *(float4*)(g_pc + pb + 4) = make_float4(cum[4], cum[5], cum[6], cum[7]);
    }
}

// ---------------------------------------------------------------------------
// Pass B: serial chunk combine. grid BH_N, 512 threads (e = tid>>3, dq = tid&7).
// s_in[ch] = carry before chunk; carry = P_ch (.) carry + s_loc[ch].
// Final carry -> Sout[b][h][d][e].
// ---------------------------------------------------------------------------
__global__ __launch_bounds__(512) void combine_kernel(float* __restrict__ Sout)
{
    int bh = blockIdx.x;
    int tid = threadIdx.x;
    int e = tid >> 3, dq = tid & 7;

    size_t sbase = (size_t)bh * CH_N * (HS_N * HS_N) + (size_t)e * HS_N + dq * 8;
    size_t pbase = (size_t)bh * CH_N * HS_N + dq * 8;

    float sc[8];
    #pragma unroll
    for (int i = 0; i < 8; i++) sc[i] = 0.f;

    // software pipeline: prefetch next chunk's (pc, sloc)
    float4 p0 = *(const float4*)(g_pc + pbase);
    float4 p1 = *(const float4*)(g_pc + pbase + 4);
    float4 l0 = *(const float4*)(g_sloc + sbase);
    float4 l1 = *(const float4*)(g_sloc + sbase + 4);

    for (int ch = 0; ch < CH_N; ch++) {
        float4 np0, np1, nl0, nl1;
        if (ch + 1 < CH_N) {
            size_t so = sbase + (size_t)(ch + 1) * (HS_N * HS_N);
            size_t po = pbase + (size_t)(ch + 1) * HS_N;
            np0 = *(const float4*)(g_pc + po);
            np1 = *(const float4*)(g_pc + po + 4);
            nl0 = *(const float4*)(g_sloc + so);
            nl1 = *(const float4*)(g_sloc + so + 4);
        }
        // write s_in for this chunk (carry before update)
        size_t so = sbase + (size_t)ch * (HS_N * HS_N);
        *(float4*)(g_sin + so)     = make_float4(sc[0], sc[1], sc[2], sc[3]);
        *(float4*)(g_sin + so + 4) = make_float4(sc[4], sc[5], sc[6], sc[7]);

        float pc[8] = {p0.x, p0.y, p0.z, p0.w, p1.x, p1.y, p1.z, p1.w};
        float sl[8] = {l0.x, l0.y, l0.z, l0.w, l1.x, l1.y, l1.z, l1.w};
        #pragma unroll
        for (int i = 0; i < 8; i++) sc[i] = fmaf(pc[i], sc[i], sl[i]);

        p0 = np0; p1 = np1; l0 = nl0; l1 = nl1;
    }

    // final state: Sout[bh][d][e], d = dq*8 + i
    size_t ob = (size_t)bh * (HS_N * HS_N) + (size_t)(dq * 8) * HS_N + e;
    #pragma unroll
    for (int i = 0; i < 8; i++) Sout[ob + (size_t)i * HS_N] = sc[i];
}

// ---------------------------------------------------------------------------
// Pass C: out_t += q_t . s_in[ch];  round to tf32 (feeds Wo GEMM).
// grid (BH_N, CH_N), 256 threads. Warp w handles t = w*4..w*4+3, lane = e, e+32.
// ---------------------------------------------------------------------------
__global__ __launch_bounds__(256) void corr_kernel()
{
    __shared__ float sq[CH_L][64];
    __shared__ float sS[64][68];

    int bh = blockIdx.x, ch = blockIdx.y;
    int b = bh >> 4, h = bh & 15;
    int tid = threadIdx.x;

    size_t qbase = (size_t)b * T_N * D_M + (size_t)ch * CH_L * D_M + h * HS_N;
    size_t sbase = ((size_t)bh * CH_N + ch) * (HS_N * HS_N);

    // load q (32x64) and s_in (64x64, [e][d])
    #pragma unroll
    for (int j = 0; j < 2; j++) {
        int f = tid + j * 256;          // 0..511
        int t = f >> 4, c = (f & 15) * 4;
        cp16(&sq[t][c], g_r + qbase + (size_t)t * D_M + c);
    }
    #pragma unroll
    for (int j = 0; j < 4; j++) {
        int f = tid + j * 256;          // 0..1023
        int ee = f >> 4, d = (f & 15) * 4;
        cp16(&sS[ee][d], g_sin + sbase + (size_t)ee * HS_N + d);
    }
    CP_COMMIT();
    cp_wait<0>();
    __syncthreads();

    int tg = tid >> 5;        // warp id: t0 = tg*4
    int el = tid & 31;        // e and e+32

    float a[4][2];
    #pragma unroll
    for (int j = 0; j < 4; j++) { a[j][0] = 0.f; a[j][1] = 0.f; }

    for (int d0 = 0; d0 < 64; d0 += 4) {
        float4 s0 = *(const float4*)&sS[el][d0];
        float4 s1 = *(const float4*)&sS[el + 32][d0];
        #pragma unroll
        for (int j = 0; j < 4; j++) {
            float4 qv = *(const float4*)&sq[tg * 4 + j][d0];
            a[j][0] = fmaf(qv.x, s0.x, fmaf(qv.y, s0.y, fmaf(qv.z, s0.z, fmaf(qv.w, s0.w, a[j][0]))));
            a[j][1] = fmaf(qv.x, s1.x, fmaf(qv.y, s1.y, fmaf(qv.z, s1.z, fmaf(qv.w, s1.w, a[j][1]))));
        }
    }

    #pragma unroll
    for (int j = 0; j < 4; j++) {
        float* p0 = g_o + qbase + (size_t)(tg * 4 + j) * D_M + el;
        float* p1 = p0 + 32;
        *p0 = to_tf32f(*p0 + a[j][0]);
        *p1 = to_tf32f(*p1 + a[j][1]);
    }
}

// ---------------------------------------------------------------------------
// Launch — kernel launches ONLY (graph-capture safe)
// ---------------------------------------------------------------------------
extern "C" void kernel_launch(void* const* d_in, const int* in_sizes, int n_in,
                              void* d_out, int out_size)
{
    const float* x    = (const float*)d_in[0];
    const float* ln_g = (const float*)d_in[1];
    const float* ln_b = (const float*)d_in[2];
    const float* Wx   = (const float*)d_in[3];
    const float* Ww   = (const float*)d_in[4];
    const float* bw   = (const float*)d_in[5];
    const float* Wk   = (const float*)d_in[6];
    const float* Wv   = (const float*)d_in[7];
    const float* Wr   = (const float*)d_in[8];
    const float* Wo   = (const float*)d_in[9];
    float* out = (float*)d_out;

    // 0) tf32-round weights into g_wt[0..5] = Wx,Ww,Wk,Wv,Wr,Wo
    round_w_kernel<<<1024, 256>>>(Wx, Ww, Wk, Wv, Wr, Wo);

    // 1) LayerNorm -> g_xn (rounded)
    ln_kernel<<<MROWS, 256>>>(x, ln_g, ln_b);

    // 2) Projections (tf32 tensor cores; operands pre-rounded)
    dim3 grid(D_M / 128, MROWS / 128);
    gemm_tc<BUF_XN, BUF_T0, 0, 4><<<grid, 128>>>(nullptr, nullptr); // t0 = xn@Wx (round)
    gemm_tc<BUF_T0, BUF_W,  1, 3><<<grid, 128>>>(bw,      nullptr); // w = sig(t0@Ww+bw)
    gemm_tc<BUF_XN, BUF_K,  2, 0><<<grid, 128>>>(nullptr, nullptr); // k
    gemm_tc<BUF_XN, BUF_V,  3, 0><<<grid, 128>>>(nullptr, nullptr); // v
    gemm_tc<BUF_XN, BUF_R,  4, 1><<<grid, 128>>>(nullptr, nullptr); // r = sig

    // 3) Chunked parallel scan
    scan_chunk_kernel<<<dim3(BH_N, CH_N), 512>>>();                 // local scans
    combine_kernel<<<BH_N, 512>>>(out + (size_t)MROWS * D_M);       // chunk combine + state
    corr_kernel<<<dim3(BH_N, CH_N), 256>>>();                       // carry-in correction

    // 4) y = o @ Wo -> head of d_out
    gemm_tc<BUF_O, BUF_EXT, 5, 0><<<grid, 128>>>(nullptr, out);
}

// round 8
// speedup vs baseline: 3.5186x; 1.1785x over previous
#include <cuda_runtime.h>
#include <math.h>
#include <stdint.h>

// Problem constants
#define D_M   1024
#define B_N   4
#define T_N   2048
#define H_N   16
#define HS_N  64
#define MROWS (B_N * T_N)   // 8192
#define CH_L  32            // chunk length
#define CH_N  (T_N / CH_L)  // 64 chunks
#define BH_N  (B_N * H_N)   // 64

#define WM_SZ ((size_t)D_M * D_M)   // 1M floats

// ---------------------------------------------------------------------------
// Scratch (static device globals)
// ---------------------------------------------------------------------------
__device__ float g_xn[(size_t)MROWS * D_M];
__device__ float g_w [(size_t)MROWS * D_M];
__device__ float g_k [(size_t)MROWS * D_M];
__device__ float g_v [(size_t)MROWS * D_M];
__device__ float g_r [(size_t)MROWS * D_M];   // becomes q after pass A
__device__ float g_o [(size_t)MROWS * D_M];
// weight pool: [0..4M) packed [Wk|Wv|Wr|Wc] (row stride 4096)
//              [4M..5M) Wx_r  [5M..6M) Ww_r  [6M..7M) Wo_r (stride 1024)
__device__ float g_wt[(size_t)7 * WM_SZ];
__device__ float g_sloc[(size_t)BH_N * CH_N * HS_N * HS_N]; // [bh][ch][e][d]
__device__ float g_sin [(size_t)BH_N * CH_N * HS_N * HS_N]; // [bh][ch][e][d]
__device__ float g_pc  [(size_t)BH_N * CH_N * HS_N];        // [bh][ch][d]

enum Buf { BUF_XN = 0, BUF_O, BUF_WXR, BUF_PACK, BUF_EXT };

template <int B> __device__ __forceinline__ float* buf_ptr(float* ext) {
    if (B == BUF_XN)   return g_xn;
    if (B == BUF_O)    return g_o;
    if (B == BUF_WXR)  return g_wt + 4 * WM_SZ;
    if (B == BUF_PACK) return g_wt;
    return ext;
}

// ---------------------------------------------------------------------------
// PTX helpers
// ---------------------------------------------------------------------------
__device__ __forceinline__ void cp16(void* smem_dst, const void* gsrc) {
    uint32_t s = (uint32_t)__cvta_generic_to_shared(smem_dst);
    asm volatile("cp.async.cg.shared.global [%0], [%1], 16;\n" :: "r"(s), "l"(gsrc));
}
#define CP_COMMIT() asm volatile("cp.async.commit_group;\n" ::: "memory")
template <int N> __device__ __forceinline__ void cp_wait() {
    asm volatile("cp.async.wait_group %0;\n" :: "n"(N) : "memory");
}
__device__ __forceinline__ float to_tf32f(float x) {
    uint32_t r;
    asm("cvt.rna.tf32.f32 %0, %1;\n" : "=r"(r) : "f"(x));
    return __uint_as_float(r);
}
__device__ __forceinline__ float4 rnd4(float4 v) {
    v.x = to_tf32f(v.x); v.y = to_tf32f(v.y);
    v.z = to_tf32f(v.z); v.w = to_tf32f(v.w);
    return v;
}
__device__ __forceinline__ void mma_tf32(float* c, const uint32_t* a, const uint32_t* b) {
    asm volatile(
        "mma.sync.aligned.m16n8k8.row.col.f32.tf32.tf32.f32 "
        "{%0,%1,%2,%3}, {%4,%5,%6,%7}, {%8,%9}, {%0,%1,%2,%3};\n"
        : "+f"(c[0]), "+f"(c[1]), "+f"(c[2]), "+f"(c[3])
        : "r"(a[0]), "r"(a[1]), "r"(a[2]), "r"(a[3]), "r"(b[0]), "r"(b[1]));
}

// ---------------------------------------------------------------------------
// round_w: tf32-round all weights. Wk,Wv,Wr -> packed slots 0..2;
// Wx -> +4M, Ww -> +5M, Wo -> +6M. grid 1024 x 256 (one float4/thread/array).
// ---------------------------------------------------------------------------
__global__ __launch_bounds__(256) void round_w_kernel(
    const float* __restrict__ Wx, const float* __restrict__ Ww,
    const float* __restrict__ Wk, const float* __restrict__ Wv,
    const float* __restrict__ Wr, const float* __restrict__ Wo)
{
    size_t idx = ((size_t)blockIdx.x * 256 + threadIdx.x) * 4;  // 0..1M step 4
    size_t k = idx >> 10, c = idx & 1023;

    // packed slots (row stride 4096)
    *(float4*)(g_wt + k * 4096 + 0 * D_M + c) = rnd4(*(const float4*)(Wk + idx));
    *(float4*)(g_wt + k * 4096 + 1 * D_M + c) = rnd4(*(const float4*)(Wv + idx));
    *(float4*)(g_wt + k * 4096 + 2 * D_M + c) = rnd4(*(const float4*)(Wr + idx));
    // plain slots
    *(float4*)(g_wt + 4 * WM_SZ + idx) = rnd4(*(const float4*)(Wx + idx));
    *(float4*)(g_wt + 5 * WM_SZ + idx) = rnd4(*(const float4*)(Ww + idx));
    *(float4*)(g_wt + 6 * WM_SZ + idx) = rnd4(*(const float4*)(Wo + idx));
}

// ---------------------------------------------------------------------------
// LayerNorm -> g_xn (tf32-rounded: feeds fused GEMM)
// ---------------------------------------------------------------------------
__global__ __launch_bounds__(256) void ln_kernel(
    const float* __restrict__ X, const float* __restrict__ G,
    const float* __restrict__ Bv)
{
    __shared__ float red[16];
    int row = blockIdx.x;
    int tid = threadIdx.x;
    const float* xr = X + (size_t)row * D_M;

    float4 xv = *(const float4*)(xr + tid * 4);
    float s = xv.x + xv.y + xv.z + xv.w;
    float q = xv.x * xv.x + xv.y * xv.y + xv.z * xv.z + xv.w * xv.w;

    #pragma unroll
    for (int o = 16; o > 0; o >>= 1) {
        s += __shfl_xor_sync(0xffffffffu, s, o);
        q += __shfl_xor_sync(0xffffffffu, q, o);
    }
    int wid = tid >> 5, lid = tid & 31;
    if (lid == 0) { red[wid] = s; red[8 + wid] = q; }
    __syncthreads();
    if (wid == 0) {
        float s2 = (lid < 8) ? red[lid] : 0.f;
        float q2 = (lid < 8) ? red[8 + lid] : 0.f;
        #pragma unroll
        for (int o = 4; o > 0; o >>= 1) {
            s2 += __shfl_xor_sync(0xffffffffu, s2, o);
            q2 += __shfl_xor_sync(0xffffffffu, q2, o);
        }
        if (lid == 0) { red[0] = s2; red[1] = q2; }
    }
    __syncthreads();

    float mu   = red[0] * (1.f / D_M);
    float var  = red[1] * (1.f / D_M) - mu * mu;
    float rstd = rsqrtf(var + 1e-5f);

    float4 gv = *(const float4*)(G + tid * 4);
    float4 bv = *(const float4*)(Bv + tid * 4);
    float4 yv;
    yv.x = to_tf32f((xv.x - mu) * rstd * gv.x + bv.x);
    yv.y = to_tf32f((xv.y - mu) * rstd * gv.y + bv.y);
    yv.z = to_tf32f((xv.z - mu) * rstd * gv.z + bv.z);
    yv.w = to_tf32f((xv.w - mu) * rstd * gv.w + bv.w);
    *(float4*)(g_xn + (size_t)row * D_M + tid * 4) = yv;
}

// ---------------------------------------------------------------------------
// GEMM core (shared by generic + fused): computes one 128x128 tile.
// 2-stage cp.async, 4 warps, warp tile 64x64. Returns acc in-place.
// A row stride = 1024 (K). W row stride = WS (template).
// ---------------------------------------------------------------------------
template <int WS>
__device__ __forceinline__ void gemm_tile(
    const float* __restrict__ A, const float* __restrict__ Wm,
    int bm, int bn, int tid, float acc[4][8][4],
    float As[2][128][20], float Bs[2][16][136])
{
    constexpr int K = D_M;

    auto load_stage = [&](int buf, int k0) {
        #pragma unroll
        for (int j = 0; j < 4; j++) {
            int f   = tid + j * 128;
            int row = f >> 2;
            int kc  = (f & 3) << 2;
            cp16(&As[buf][row][kc], A + (size_t)(bm + row) * K + k0 + kc);
        }
        #pragma unroll
        for (int j = 0; j < 4; j++) {
            int f  = tid + j * 128;
            int kr = f >> 5;
            int nc = (f & 31) << 2;
            cp16(&Bs[buf][kr][nc], Wm + (size_t)(k0 + kr) * WS + bn + nc);
        }
        CP_COMMIT();
    };

    int wid = tid >> 5, lane = tid & 31;
    int g = lane >> 2, cq = lane & 3;
    int wm = (wid & 1) * 64, wn = (wid >> 1) * 64;

    load_stage(0, 0);

    for (int kt = 0; kt < K / 16; kt++) {
        int buf = kt & 1;
        if (kt < K / 16 - 1) {
            load_stage(buf ^ 1, (kt + 1) * 16);
            cp_wait<1>();
        } else {
            cp_wait<0>();
        }
        __syncthreads();

        #pragma unroll
        for (int ks = 0; ks < 2; ks++) {
            uint32_t af[4][4], bf[8][2];
            #pragma unroll
            for (int mi = 0; mi < 4; mi++) {
                int r0 = wm + mi * 16 + g;
                af[mi][0] = *(const uint32_t*)&As[buf][r0    ][ks * 8 + cq];
                af[mi][1] = *(const uint32_t*)&As[buf][r0 + 8][ks * 8 + cq];
                af[mi][2] = *(const uint32_t*)&As[buf][r0    ][ks * 8 + cq + 4];
                af[mi][3] = *(const uint32_t*)&As[buf][r0 + 8][ks * 8 + cq + 4];
            }
            #pragma unroll
            for (int ni = 0; ni < 8; ni++) {
                int c0 = wn + ni * 8 + g;
                bf[ni][0] = *(const uint32_t*)&Bs[buf][ks * 8 + cq    ][c0];
                bf[ni][1] = *(const uint32_t*)&Bs[buf][ks * 8 + cq + 4][c0];
            }
            #pragma unroll
            for (int mi = 0; mi < 4; mi++)
                #pragma unroll
                for (int ni = 0; ni < 8; ni++)
                    mma_tf32(acc[mi][ni], af[mi], bf[ni]);
        }
        __syncthreads();
    }
}

// ---------------------------------------------------------------------------
// Generic GEMM: C = act(A @ W); A from buf, W at g_wt+WOFF*1M (stride 1024),
// C = buf(CSEL)+COFF with row stride CS. FLAGS: bit0 sigmoid, bit2 round.
// ---------------------------------------------------------------------------
template <int ASEL, int CSEL, int WOFF, int COFF, int CS, int FLAGS>
__global__ __launch_bounds__(128) void gemm_tc(float* __restrict__ Cext)
{
    __shared__ float As[2][128][20];
    __shared__ float Bs[2][16][136];

    const float* A  = buf_ptr<ASEL>(nullptr);
    const float* Wm = g_wt + (size_t)WOFF * WM_SZ;
    float*       C  = buf_ptr<CSEL>(Cext) + COFF;

    int tid = threadIdx.x;
    int bm = blockIdx.y * 128, bn = blockIdx.x * 128;

    float acc[4][8][4];
    #pragma unroll
    for (int mi = 0; mi < 4; mi++)
        #pragma unroll
        for (int ni = 0; ni < 8; ni++)
            #pragma unroll
            for (int x = 0; x < 4; x++) acc[mi][ni][x] = 0.f;

    gemm_tile<D_M>(A, Wm, bm, bn, tid, acc, As, Bs);

    int wid = tid >> 5, lane = tid & 31;
    int g = lane >> 2, cq = lane & 3;
    int wm = (wid & 1) * 64, wn = (wid >> 1) * 64;

    #pragma unroll
    for (int mi = 0; mi < 4; mi++) {
        int row0 = bm + wm + mi * 16 + g;
        #pragma unroll
        for (int ni = 0; ni < 8; ni++) {
            int col = bn + wn + ni * 8 + cq * 2;
            float v0 = acc[mi][ni][0];
            float v1 = acc[mi][ni][1];
            float v2 = acc[mi][ni][2];
            float v3 = acc[mi][ni][3];
            if (FLAGS & 1) {
                v0 = 1.f / (1.f + expf(-v0));
                v1 = 1.f / (1.f + expf(-v1));
                v2 = 1.f / (1.f + expf(-v2));
                v3 = 1.f / (1.f + expf(-v3));
            }
            if (FLAGS & 4) {
                v0 = to_tf32f(v0); v1 = to_tf32f(v1);
                v2 = to_tf32f(v2); v3 = to_tf32f(v3);
            }
            *(float2*)(C + (size_t)row0 * CS + col)       = make_float2(v0, v1);
            *(float2*)(C + (size_t)(row0 + 8) * CS + col) = make_float2(v2, v3);
        }
    }
}

// ---------------------------------------------------------------------------
// Fused projection GEMM: xn[8192][1024] @ packed[1024][4096].
// n-slab 0 -> g_k, 1 -> g_v, 2 -> sigmoid -> g_r, 3 -> sigmoid(+bw) -> g_w.
// grid (32, 64).
// ---------------------------------------------------------------------------
__global__ __launch_bounds__(128) void gemm_fused(const float* __restrict__ bw)
{
    __shared__ float As[2][128][20];
    __shared__ float Bs[2][16][136];

    int tid = threadIdx.x;
    int bm = blockIdx.y * 128, bn = blockIdx.x * 128;

    float acc[4][8][4];
    #pragma unroll
    for (int mi = 0; mi < 4; mi++)
        #pragma unroll
        for (int ni = 0; ni < 8; ni++)
            #pragma unroll
            for (int x = 0; x < 4; x++) acc[mi][ni][x] = 0.f;

    gemm_tile<4096>(g_xn, g_wt, bm, bn, tid, acc, As, Bs);

    int wid = tid >> 5, lane = tid & 31;
    int g = lane >> 2, cq = lane & 3;
    int wm = (wid & 1) * 64, wn = (wid >> 1) * 64;

    int nb = bn >> 10;          // slab
    int nc0 = bn & 1023;        // local col base
    float* dest = (nb == 0) ? g_k : (nb == 1) ? g_v : (nb == 2) ? g_r : g_w;
    bool sig = (nb >= 2);
    bool hasb = (nb == 3);

    #pragma unroll
    for (int mi = 0; mi < 4; mi++) {
        int row0 = bm + wm + mi * 16 + g;
        #pragma unroll
        for (int ni = 0; ni < 8; ni++) {
            int col = nc0 + wn + ni * 8 + cq * 2;
            float b0 = hasb ? bw[col]     : 0.f;
            float b1 = hasb ? bw[col + 1] : 0.f;
            float v0 = acc[mi][ni][0] + b0;
            float v1 = acc[mi][ni][1] + b1;
            float v2 = acc[mi][ni][2] + b0;
            float v3 = acc[mi][ni][3] + b1;
            if (sig) {
                v0 = 1.f / (1.f + expf(-v0));
                v1 = 1.f / (1.f + expf(-v1));
                v2 = 1.f / (1.f + expf(-v2));
                v3 = 1.f / (1.f + expf(-v3));
            }
            *(float2*)(dest + (size_t)row0 * D_M + col)       = make_float2(v0, v1);
            *(float2*)(dest + (size_t)(row0 + 8) * D_M + col) = make_float2(v2, v3);
        }
    }
}

// ---------------------------------------------------------------------------
// Pass A: per-chunk local scan. grid (BH_N, CH_N), 512 threads.
// ---------------------------------------------------------------------------
__global__ __launch_bounds__(512) void scan_chunk_kernel()
{
    __shared__ float sk[CH_L][64], sw[CH_L][64], sr[CH_L][64], sv[CH_L][64];

    int bh = blockIdx.x, ch = blockIdx.y;
    int b = bh >> 4, h = bh & 15;
    int tid = threadIdx.x;
    int e = tid >> 3, dq = tid & 7;

    size_t base = (size_t)b * T_N * D_M + (size_t)ch * CH_L * D_M + h * HS_N;

    {
        int t = tid >> 4, c = (tid & 15) * 4;
        size_t off = base + (size_t)t * D_M + c;
        cp16(&sk[t][c], g_k + off);
        cp16(&sw[t][c], g_w + off);
        cp16(&sr[t][c], g_r + off);
        cp16(&sv[t][c], g_v + off);
    }
    CP_COMMIT();
    cp_wait<0>();
    __syncthreads();

    float s[8], cum[8];
    #pragma unroll
    for (int i = 0; i < 8; i++) { s[i] = 0.f; cum[i] = 1.f; }

    float* op = g_o + base + e;
    float* qp = g_r + base + dq * 8;

    for (int t = 0; t < CH_L; t++) {
        float4 k0 = *(const float4*)&sk[t][dq * 8];
        float4 k1 = *(const float4*)&sk[t][dq * 8 + 4];
        float4 w0 = *(const float4*)&sw[t][dq * 8];
        float4 w1 = *(const float4*)&sw[t][dq * 8 + 4];
        float4 r0 = *(const float4*)&sr[t][dq * 8];
        float4 r1 = *(const float4*)&sr[t][dq * 8 + 4];
        float vv  = sv[t][e];

        float kc[8] = {k0.x, k0.y, k0.z, k0.w, k1.x, k1.y, k1.z, k1.w};
        float wc[8] = {w0.x, w0.y, w0.z, w0.w, w1.x, w1.y, w1.z, w1.w};
        float rc[8] = {r0.x, r0.y, r0.z, r0.w, r1.x, r1.y, r1.z, r1.w};

        float acc = 0.f;
        #pragma unroll
        for (int i = 0; i < 8; i++) {
            float omw = 1.f - wc[i];
            cum[i] *= omw;
            float si = fmaf(kc[i], vv, s[i] * omw);
            s[i] = si;
            acc = fmaf(rc[i], si, acc);
        }
        acc += __shfl_xor_sync(0xffffffffu, acc, 1);
        acc += __shfl_xor_sync(0xffffffffu, acc, 2);
        acc += __shfl_xor_sync(0xffffffffu, acc, 4);
        if (dq == 0) *op = acc;
        op += D_M;

        if (e == 0) {
            float q[8];
            #pragma unroll
            for (int i = 0; i < 8; i++) q[i] = rc[i] * cum[i];
            *(float4*)(qp)     = make_float4(q[0], q[1], q[2], q[3]);
            *(float4*)(qp + 4) = make_float4(q[4], q[5], q[6], q[7]);
        }
        qp += D_M;
    }

    size_t sb = ((size_t)bh * CH_N + ch) * (HS_N * HS_N) + (size_t)e * HS_N + dq * 8;
    *(float4*)(g_sloc + sb)     = make_float4(s[0], s[1], s[2], s[3]);
    *(float4*)(g_sloc + sb + 4) = make_float4(s[4], s[5], s[6], s[7]);

    if (e == 0) {
        size_t pb = ((size_t)bh * CH_N + ch) * HS_N + dq * 8;
        *(float4*)(g_pc + pb)     = make_float4(cum[0], cum[1], cum[2], cum[3]);
        *(float4*)(g_pc + pb + 4) = make_float4(cum[4], cum[5], cum[6], cum[7]);
    }
}

// ---------------------------------------------------------------------------
// Pass B: serial chunk combine. grid BH_N, 512 threads.
// ---------------------------------------------------------------------------
__global__ __launch_bounds__(512) void combine_kernel(float* __restrict__ Sout)
{
    int bh = blockIdx.x;
    int tid = threadIdx.x;
    int e = tid >> 3, dq = tid & 7;

    size_t sbase = (size_t)bh * CH_N * (HS_N * HS_N) + (size_t)e * HS_N + dq * 8;
    size_t pbase = (size_t)bh * CH_N * HS_N + dq * 8;

    float sc[8];
    #pragma unroll
    for (int i = 0; i < 8; i++) sc[i] = 0.f;

    float4 p0 = *(const float4*)(g_pc + pbase);
    float4 p1 = *(const float4*)(g_pc + pbase + 4);
    float4 l0 = *(const float4*)(g_sloc + sbase);
    float4 l1 = *(const float4*)(g_sloc + sbase + 4);

    for (int ch = 0; ch < CH_N; ch++) {
        float4 np0, np1, nl0, nl1;
        if (ch + 1 < CH_N) {
            size_t so = sbase + (size_t)(ch + 1) * (HS_N * HS_N);
            size_t po = pbase + (size_t)(ch + 1) * HS_N;
            np0 = *(const float4*)(g_pc + po);
            np1 = *(const float4*)(g_pc + po + 4);
            nl0 = *(const float4*)(g_sloc + so);
            nl1 = *(const float4*)(g_sloc + so + 4);
        }
        size_t so = sbase + (size_t)ch * (HS_N * HS_N);
        *(float4*)(g_sin + so)     = make_float4(sc[0], sc[1], sc[2], sc[3]);
        *(float4*)(g_sin + so + 4) = make_float4(sc[4], sc[5], sc[6], sc[7]);

        float pc[8] = {p0.x, p0.y, p0.z, p0.w, p1.x, p1.y, p1.z, p1.w};
        float sl[8] = {l0.x, l0.y, l0.z, l0.w, l1.x, l1.y, l1.z, l1.w};
        #pragma unroll
        for (int i = 0; i < 8; i++) sc[i] = fmaf(pc[i], sc[i], sl[i]);

        p0 = np0; p1 = np1; l0 = nl0; l1 = nl1;
    }

    size_t ob = (size_t)bh * (HS_N * HS_N) + (size_t)(dq * 8) * HS_N + e;
    #pragma unroll
    for (int i = 0; i < 8; i++) Sout[ob + (size_t)i * HS_N] = sc[i];
}

// ---------------------------------------------------------------------------
// Pass C: out_t += q_t . s_in[ch]; round to tf32. grid (BH_N, CH_N), 256 thr.
// ---------------------------------------------------------------------------
__global__ __launch_bounds__(256) void corr_kernel()
{
    __shared__ float sq[CH_L][64];
    __shared__ float sS[64][68];

    int bh = blockIdx.x, ch = blockIdx.y;
    int b = bh >> 4, h = bh & 15;
    int tid = threadIdx.x;

    size_t qbase = (size_t)b * T_N * D_M + (size_t)ch * CH_L * D_M + h * HS_N;
    size_t sbase = ((size_t)bh * CH_N + ch) * (HS_N * HS_N);

    #pragma unroll
    for (int j = 0; j < 2; j++) {
        int f = tid + j * 256;
        int t = f >> 4, c = (f & 15) * 4;
        cp16(&sq[t][c], g_r + qbase + (size_t)t * D_M + c);
    }
    #pragma unroll
    for (int j = 0; j < 4; j++) {
        int f = tid + j * 256;
        int ee = f >> 4, d = (f & 15) * 4;
        cp16(&sS[ee][d], g_sin + sbase + (size_t)ee * HS_N + d);
    }
    CP_COMMIT();
    cp_wait<0>();
    __syncthreads();

    int tg = tid >> 5;
    int el = tid & 31;

    float a[4][2];
    #pragma unroll
    for (int j = 0; j < 4; j++) { a[j][0] = 0.f; a[j][1] = 0.f; }

    for (int d0 = 0; d0 < 64; d0 += 4) {
        float4 s0 = *(const float4*)&sS[el][d0];
        float4 s1 = *(const float4*)&sS[el + 32][d0];
        #pragma unroll
        for (int j = 0; j < 4; j++) {
            float4 qv = *(const float4*)&sq[tg * 4 + j][d0];
            a[j][0] = fmaf(qv.x, s0.x, fmaf(qv.y, s0.y, fmaf(qv.z, s0.z, fmaf(qv.w, s0.w, a[j][0]))));
            a[j][1] = fmaf(qv.x, s1.x, fmaf(qv.y, s1.y, fmaf(qv.z, s1.z, fmaf(qv.w, s1.w, a[j][1]))));
        }
    }

    #pragma unroll
    for (int j = 0; j < 4; j++) {
        float* p0 = g_o + qbase + (size_t)(tg * 4 + j) * D_M + el;
        float* p1 = p0 + 32;
        *p0 = to_tf32f(*p0 + a[j][0]);
        *p1 = to_tf32f(*p1 + a[j][1]);
    }
}

// ---------------------------------------------------------------------------
// Launch — kernel launches ONLY (graph-capture safe)
// ---------------------------------------------------------------------------
extern "C" void kernel_launch(void* const* d_in, const int* in_sizes, int n_in,
                              void* d_out, int out_size)
{
    const float* x    = (const float*)d_in[0];
    const float* ln_g = (const float*)d_in[1];
    const float* ln_b = (const float*)d_in[2];
    const float* Wx   = (const float*)d_in[3];
    const float* Ww   = (const float*)d_in[4];
    const float* bw   = (const float*)d_in[5];
    const float* Wk   = (const float*)d_in[6];
    const float* Wv   = (const float*)d_in[7];
    const float* Wr   = (const float*)d_in[8];
    const float* Wo   = (const float*)d_in[9];
    float* out = (float*)d_out;

    // 0) round + pack weights
    round_w_kernel<<<1024, 256>>>(Wx, Ww, Wk, Wv, Wr, Wo);

    // 0b) Wc = round(Wx_r @ Ww_r) into packed slab 3 (8x8 = 64 blocks)
    gemm_tc<BUF_WXR, BUF_PACK, 5, 3 * D_M, 4096, 4><<<dim3(8, 8), 128>>>(nullptr);

    // 1) LayerNorm -> g_xn (rounded)
    ln_kernel<<<MROWS, 256>>>(x, ln_g, ln_b);

    // 2) Fused projections: k, v, r=sig, w=sig(+bw)  (32 x 64 = 2048 blocks)
    gemm_fused<<<dim3(32, 64), 128>>>(bw);

    // 3) Chunked parallel scan
    scan_chunk_kernel<<<dim3(BH_N, CH_N), 512>>>();
    combine_kernel<<<BH_N, 512>>>(out + (size_t)MROWS * D_M);
    corr_kernel<<<dim3(BH_N, CH_N), 256>>>();

    // 4) y = o @ Wo -> head of d_out  (8 x 64 = 512 blocks)
    gemm_tc<BUF_O, BUF_EXT, 6, 0, D_M, 0><<<dim3(8, 64), 128>>>(out);
}